// round 1
// baseline (speedup 1.0000x reference)
#include <cuda_runtime.h>
#include <math.h>

#define BATCH 2
#define TSEQ  2048
#define DMODEL 1024
#define NHEAD 16
#define DHEAD 64
#define BT (BATCH * TSEQ)          // 4096
#define QKV_N (3 * DMODEL)         // 3072

// Scratch (allocation-free rule: device globals)
__device__ float g_qkv[(size_t)BT * QKV_N];    // [4096, 3072]
__device__ float g_attn[(size_t)BT * DMODEL];  // [4096, 1024]

// ---------------------------------------------------------------------------
// SGEMM: C[M,N] = A[M,K] @ B[K,N] + bias[N]
// BM=BN=128, BK=8, TM=TN=8, 256 threads. All dims divisible by tiles here.
// ---------------------------------------------------------------------------
__global__ __launch_bounds__(256) void sgemm_bias_kernel(
    int M, int N, int K,
    const float* __restrict__ A,
    const float* __restrict__ B,
    const float* __restrict__ bias,
    float* __restrict__ C)
{
    const int BM = 128, BN = 128, BK = 8;
    __shared__ float As[BK][BM];
    __shared__ float Bs[BK][BN];

    const int tid  = threadIdx.x;
    const int brow = blockIdx.y;     // M tile
    const int bcol = blockIdx.x;     // N tile

    const float* Ab = A + (size_t)brow * BM * K;
    const float* Bb = B + (size_t)bcol * BN;

    // A tile load: 128x8 floats, one float4 per thread
    const int a_r = tid >> 1;                 // 0..127
    const int a_c = (tid & 1) * 4;            // 0 or 4
    // B tile load: 8x128 floats, one float4 per thread
    const int b_r = tid >> 5;                 // 0..7
    const int b_c = (tid & 31) * 4;           // 0..124

    const int tr = (tid >> 4) * 8;            // 0..120
    const int tc = (tid & 15) * 8;            // 0..120

    float acc[8][8];
#pragma unroll
    for (int i = 0; i < 8; i++)
#pragma unroll
        for (int j = 0; j < 8; j++) acc[i][j] = 0.f;

    for (int k0 = 0; k0 < K; k0 += BK) {
        float4 a4 = *(const float4*)(Ab + (size_t)a_r * K + k0 + a_c);
        As[a_c + 0][a_r] = a4.x;
        As[a_c + 1][a_r] = a4.y;
        As[a_c + 2][a_r] = a4.z;
        As[a_c + 3][a_r] = a4.w;
        *(float4*)&Bs[b_r][b_c] =
            *(const float4*)(Bb + (size_t)(k0 + b_r) * N + b_c);
        __syncthreads();

#pragma unroll
        for (int k = 0; k < BK; k++) {
            float ra[8], rb[8];
            float4 t0 = *(const float4*)&As[k][tr];
            float4 t1 = *(const float4*)&As[k][tr + 4];
            ra[0]=t0.x; ra[1]=t0.y; ra[2]=t0.z; ra[3]=t0.w;
            ra[4]=t1.x; ra[5]=t1.y; ra[6]=t1.z; ra[7]=t1.w;
            float4 u0 = *(const float4*)&Bs[k][tc];
            float4 u1 = *(const float4*)&Bs[k][tc + 4];
            rb[0]=u0.x; rb[1]=u0.y; rb[2]=u0.z; rb[3]=u0.w;
            rb[4]=u1.x; rb[5]=u1.y; rb[6]=u1.z; rb[7]=u1.w;
#pragma unroll
            for (int i = 0; i < 8; i++)
#pragma unroll
                for (int j = 0; j < 8; j++)
                    acc[i][j] = fmaf(ra[i], rb[j], acc[i][j]);
        }
        __syncthreads();
    }

#pragma unroll
    for (int i = 0; i < 8; i++) {
        float* crow = C + (size_t)(brow * BM + tr + i) * N + bcol * BN + tc;
        const float* brow_ptr = bias + bcol * BN + tc;
#pragma unroll
        for (int j = 0; j < 8; j += 4) {
            float4 o;
            o.x = acc[i][j + 0] + brow_ptr[j + 0];
            o.y = acc[i][j + 1] + brow_ptr[j + 1];
            o.z = acc[i][j + 2] + brow_ptr[j + 2];
            o.w = acc[i][j + 3] + brow_ptr[j + 3];
            *(float4*)(crow + j) = o;
        }
    }
}

// ---------------------------------------------------------------------------
// Causal flash attention, fp32. One query per thread, 128 queries / block.
// K/V tiles of 64 keys x 64 dims in smem. Online softmax in chunks of 8 keys.
// qkv layout: [BT, 3072]; q at +0, k at +1024, v at +2048, head offset h*64.
// out: [BT, 1024] with head-merged layout out[b,t, h*64+d].
// ---------------------------------------------------------------------------
__global__ __launch_bounds__(128) void attn_kernel(
    const float* __restrict__ qkv, float* __restrict__ out)
{
    const int b  = blockIdx.z;
    const int h  = blockIdx.y;
    const int qi = blockIdx.x * 128 + threadIdx.x;   // token index in [0, TSEQ)

    __shared__ float Ks[64][DHEAD];
    __shared__ float Vs[64][DHEAD];

    // Load this thread's query row, pre-scaled by 1/sqrt(dh)
    float q[DHEAD];
    {
        const float* qp = qkv + ((size_t)(b * TSEQ + qi)) * QKV_N + h * DHEAD;
#pragma unroll
        for (int d = 0; d < DHEAD; d += 4) {
            float4 v = *(const float4*)(qp + d);
            q[d + 0] = v.x * 0.125f;
            q[d + 1] = v.y * 0.125f;
            q[d + 2] = v.z * 0.125f;
            q[d + 3] = v.w * 0.125f;
        }
    }

    float acc[DHEAD];
#pragma unroll
    for (int d = 0; d < DHEAD; d++) acc[d] = 0.f;
    float m = -1e30f, l = 0.f;

    const int ntiles = blockIdx.x * 2 + 2;   // keys 0 .. blockIdx.x*128+127
    for (int kt = 0; kt < ntiles; kt++) {
        __syncthreads();
        // cooperative load of 64x64 K and V tiles (float4, coalesced)
        for (int i = threadIdx.x; i < 64 * (DHEAD / 4); i += 128) {
            int r  = i >> 4;          // key row in tile
            int c4 = i & 15;          // float4 column
            size_t base = ((size_t)(b * TSEQ + kt * 64 + r)) * QKV_N
                        + h * DHEAD + c4 * 4;
            *(float4*)&Ks[r][c4 * 4] = *(const float4*)(qkv + base + DMODEL);
            *(float4*)&Vs[r][c4 * 4] = *(const float4*)(qkv + base + 2 * DMODEL);
        }
        __syncthreads();

        const int kbase = kt * 64;
#pragma unroll 1
        for (int jc = 0; jc < 64; jc += 8) {
            float s[8];
#pragma unroll
            for (int j = 0; j < 8; j++) s[j] = 0.f;
#pragma unroll
            for (int d4 = 0; d4 < DHEAD / 4; d4++) {
                float q0 = q[d4*4+0], q1 = q[d4*4+1], q2 = q[d4*4+2], q3 = q[d4*4+3];
#pragma unroll
                for (int j = 0; j < 8; j++) {
                    float4 kv = *(const float4*)&Ks[jc + j][d4 * 4];
                    s[j] = fmaf(q0, kv.x, s[j]);
                    s[j] = fmaf(q1, kv.y, s[j]);
                    s[j] = fmaf(q2, kv.z, s[j]);
                    s[j] = fmaf(q3, kv.w, s[j]);
                }
            }
            // causal mask
            float mloc = m;
#pragma unroll
            for (int j = 0; j < 8; j++) {
                if (kbase + jc + j > qi) s[j] = -1e30f;
                mloc = fmaxf(mloc, s[j]);
            }
            if (mloc > m) {
                float corr = __expf(m - mloc);
                l *= corr;
#pragma unroll
                for (int d = 0; d < DHEAD; d++) acc[d] *= corr;
                m = mloc;
            }
            float p[8];
#pragma unroll
            for (int j = 0; j < 8; j++) {
                p[j] = __expf(s[j] - m);
                l += p[j];
            }
#pragma unroll
            for (int d4 = 0; d4 < DHEAD / 4; d4++) {
                float a0 = acc[d4*4+0], a1 = acc[d4*4+1],
                      a2 = acc[d4*4+2], a3 = acc[d4*4+3];
#pragma unroll
                for (int j = 0; j < 8; j++) {
                    float4 vv = *(const float4*)&Vs[jc + j][d4 * 4];
                    a0 = fmaf(p[j], vv.x, a0);
                    a1 = fmaf(p[j], vv.y, a1);
                    a2 = fmaf(p[j], vv.z, a2);
                    a3 = fmaf(p[j], vv.w, a3);
                }
                acc[d4*4+0] = a0; acc[d4*4+1] = a1;
                acc[d4*4+2] = a2; acc[d4*4+3] = a3;
            }
        }
    }

    const float inv = 1.f / l;
    float* op = out + ((size_t)(b * TSEQ + qi)) * DMODEL + h * DHEAD;
#pragma unroll
    for (int d = 0; d < DHEAD; d += 4) {
        float4 o;
        o.x = acc[d + 0] * inv;
        o.y = acc[d + 1] * inv;
        o.z = acc[d + 2] * inv;
        o.w = acc[d + 3] * inv;
        *(float4*)(op + d) = o;
    }
}

// ---------------------------------------------------------------------------
extern "C" void kernel_launch(void* const* d_in, const int* in_sizes, int n_in,
                              void* d_out, int out_size)
{
    const float* x      = (const float*)d_in[0];   // [2,2048,1024]
    const float* W_attn = (const float*)d_in[1];   // [1024,3072]
    const float* b_attn = (const float*)d_in[2];   // [3072]
    const float* W_proj = (const float*)d_in[3];   // [1024,1024]
    const float* b_proj = (const float*)d_in[4];   // [1024]
    float* out = (float*)d_out;                    // [2,2048,1024]

    float* qkv  = nullptr;
    float* attn = nullptr;
    cudaGetSymbolAddress((void**)&qkv,  g_qkv);
    cudaGetSymbolAddress((void**)&attn, g_attn);

    // 1) QKV projection: [4096,1024] @ [1024,3072] + bias
    {
        dim3 grid(QKV_N / 128, BT / 128);
        sgemm_bias_kernel<<<grid, 256>>>(BT, QKV_N, DMODEL, x, W_attn, b_attn, qkv);
    }
    // 2) Causal multi-head attention
    {
        dim3 grid(TSEQ / 128, NHEAD, BATCH);
        attn_kernel<<<grid, 128>>>(qkv, attn);
    }
    // 3) Output projection: [4096,1024] @ [1024,1024] + bias
    {
        dim3 grid(DMODEL / 128, BT / 128);
        sgemm_bias_kernel<<<grid, 256>>>(BT, DMODEL, DMODEL, attn, W_proj, b_proj, out);
    }
}

// round 3
// speedup vs baseline: 1.4926x; 1.4926x over previous
#include <cuda_runtime.h>
#include <cstdint>
#include <math.h>

#define BATCH 2
#define TSEQ  2048
#define DMODEL 1024
#define NHEAD 16
#define DHEAD 64
#define BT (BATCH * TSEQ)          // 4096
#define QKV_N (3 * DMODEL)         // 3072
#define KDIM DMODEL                // K = 1024 for both GEMMs

// ---------------- scratch (device globals; allocation-free rule) ----------
__device__ __align__(256) float g_qkv[(size_t)BT * QKV_N];       // [4096,3072]
__device__ __align__(256) float g_attn[(size_t)BT * DMODEL];     // [4096,1024]
__device__ __align__(256) float g_xr[(size_t)BT * DMODEL];       // x, tf32-rounded
__device__ __align__(256) float g_wt_attn[(size_t)QKV_N * KDIM]; // W_attn^T [3072,1024]
__device__ __align__(256) float g_wt_proj[(size_t)DMODEL * KDIM];// W_proj^T [1024,1024]

// ---------------- helpers ---------------------------------------------------
__device__ __forceinline__ uint32_t smem_u32(const void* p) {
    uint32_t a;
    asm("{ .reg .u64 t; cvta.to.shared.u64 t, %1; cvt.u32.u64 %0, t; }" : "=r"(a) : "l"(p));
    return a;
}
__device__ __forceinline__ float rna_tf32(float x) {
    float r;
    asm("cvt.rna.tf32.f32 %0, %1;" : "=f"(r) : "f"(x));
    return r;
}
__device__ __forceinline__ void cp_async16(uint32_t saddr, const void* gptr) {
    asm volatile("cp.async.cg.shared.global [%0], [%1], 16;" :: "r"(saddr), "l"(gptr));
}
__device__ __forceinline__ void mma_tf32_16n8k8(float* d, const uint32_t* a, const uint32_t* b) {
    asm volatile(
        "mma.sync.aligned.m16n8k8.row.col.f32.tf32.tf32.f32 "
        "{%0,%1,%2,%3}, {%4,%5,%6,%7}, {%8,%9}, {%0,%1,%2,%3};"
        : "+f"(d[0]), "+f"(d[1]), "+f"(d[2]), "+f"(d[3])
        : "r"(a[0]), "r"(a[1]), "r"(a[2]), "r"(a[3]), "r"(b[0]), "r"(b[1]));
}

// ---------------- prep kernels ---------------------------------------------
__global__ void round_tf32_kernel(const float4* __restrict__ src,
                                  float4* __restrict__ dst, int n4) {
    int i = blockIdx.x * blockDim.x + threadIdx.x;
    if (i < n4) {
        float4 v = src[i];
        v.x = rna_tf32(v.x); v.y = rna_tf32(v.y);
        v.z = rna_tf32(v.z); v.w = rna_tf32(v.w);
        dst[i] = v;
    }
}

// Wt[n][k] = rna(W[k][n]);  W is [K, N] row-major
__global__ void transpose_rna_kernel(const float* __restrict__ W,
                                     float* __restrict__ Wt, int K, int N) {
    __shared__ float tile[32][33];
    int nx = blockIdx.x * 32, kx = blockIdx.y * 32;
    for (int i = threadIdx.y; i < 32; i += 8)
        tile[i][threadIdx.x] = W[(size_t)(kx + i) * N + nx + threadIdx.x];
    __syncthreads();
    for (int i = threadIdx.y; i < 32; i += 8)
        Wt[(size_t)(nx + i) * K + kx + threadIdx.x] = rna_tf32(tile[threadIdx.x][i]);
}

// ---------------- tf32 mma.sync GEMM ---------------------------------------
// C[M,N] = A[M,K] @ Bt[N,K]^T + bias[N].  CTA tile 128x128, BK=32, 256 threads.
// Warp grid 2(m) x 4(n): each warp 64x32 via 4x4 m16n8k8 mma's per k8-step.
// Smem layout: As[2][128][36], Bs[2][128][36] floats.  Stride 36 makes the
// fragment LDS pattern (4*row + k) % 32 a perfect bank permutation.
#define GSTRIDE 36
#define GBUF (128 * GSTRIDE)        // floats per buffer
#define GEMM_SMEM (2 * 2 * GBUF * 4) // bytes = 73728

__global__ __launch_bounds__(256) void gemm_tf32_mma(
    const float* __restrict__ A, const float* __restrict__ Bt,
    const float* __restrict__ bias, float* __restrict__ C, int N)
{
    extern __shared__ float sm[];
    float* As = sm;                  // [2][128][36]
    float* Bs = sm + 2 * GBUF;       // [2][128][36]

    const int tid = threadIdx.x, wid = tid >> 5, lid = tid & 31;
    const int m0 = blockIdx.y * 128, n0 = blockIdx.x * 128;
    const int m_warp = (wid >> 2) * 64;   // 0 or 64
    const int n_warp = (wid & 3) * 32;    // 0,32,64,96

    const uint32_t sA = smem_u32(As), sB = smem_u32(Bs);

    // cp.async addressing: 1024 16B chunks per tile, 4 per thread
    const int ch_row = (tid * 4 + 0) >> 3;  // with 4 consecutive chunks per thread:
    // simpler: chunk = tid + i*256
    float acc[4][4][4];
#pragma unroll
    for (int i = 0; i < 4; i++)
#pragma unroll
        for (int j = 0; j < 4; j++)
#pragma unroll
            for (int q = 0; q < 4; q++) acc[i][j][q] = 0.f;
    (void)ch_row;

    auto load_stage = [&](int c, int buf) {
        const int k0 = c * 32;
#pragma unroll
        for (int i = 0; i < 4; i++) {
            int ch = tid + i * 256;
            int row = ch >> 3, c16 = ch & 7;
            uint32_t so = (uint32_t)((buf * GBUF + row * GSTRIDE + c16 * 4) * 4);
            cp_async16(sA + so, A + (size_t)(m0 + row) * KDIM + k0 + c16 * 4);
            cp_async16(sB + so, Bt + (size_t)(n0 + row) * KDIM + k0 + c16 * 4);
        }
        asm volatile("cp.async.commit_group;" ::: "memory");
    };

    load_stage(0, 0);

    const int NCHUNK = KDIM / 32;   // 32
    for (int c = 0; c < NCHUNK; c++) {
        if (c + 1 < NCHUNK) {
            load_stage(c + 1, (c + 1) & 1);
            asm volatile("cp.async.wait_group 1;" ::: "memory");
        } else {
            asm volatile("cp.async.wait_group 0;" ::: "memory");
        }
        __syncthreads();

        const float* Ab = As + (c & 1) * GBUF;
        const float* Bb = Bs + (c & 1) * GBUF;
#pragma unroll
        for (int ks = 0; ks < 4; ks++) {
            const int k_lo = ks * 8 + (lid & 3);
            uint32_t af[4][4], bf[4][2];
#pragma unroll
            for (int mt = 0; mt < 4; mt++) {
                int r0 = m_warp + mt * 16 + (lid >> 2);
                af[mt][0] = __float_as_uint(Ab[r0 * GSTRIDE + k_lo]);
                af[mt][1] = __float_as_uint(Ab[(r0 + 8) * GSTRIDE + k_lo]);
                af[mt][2] = __float_as_uint(Ab[r0 * GSTRIDE + k_lo + 4]);
                af[mt][3] = __float_as_uint(Ab[(r0 + 8) * GSTRIDE + k_lo + 4]);
            }
#pragma unroll
            for (int nt = 0; nt < 4; nt++) {
                int nc = n_warp + nt * 8 + (lid >> 2);
                bf[nt][0] = __float_as_uint(Bb[nc * GSTRIDE + k_lo]);
                bf[nt][1] = __float_as_uint(Bb[nc * GSTRIDE + k_lo + 4]);
            }
#pragma unroll
            for (int mt = 0; mt < 4; mt++)
#pragma unroll
                for (int nt = 0; nt < 4; nt++)
                    mma_tf32_16n8k8(acc[mt][nt], af[mt], bf[nt]);
        }
        __syncthreads();
    }

    // epilogue: direct float2 stores + bias
#pragma unroll
    for (int mt = 0; mt < 4; mt++) {
        int r0 = m0 + m_warp + mt * 16 + (lid >> 2);
#pragma unroll
        for (int nt = 0; nt < 4; nt++) {
            int cb = n0 + n_warp + nt * 8 + 2 * (lid & 3);
            float2 bz = *(const float2*)(bias + cb);
            float2 o0, o1;
            o0.x = acc[mt][nt][0] + bz.x; o0.y = acc[mt][nt][1] + bz.y;
            o1.x = acc[mt][nt][2] + bz.x; o1.y = acc[mt][nt][3] + bz.y;
            *(float2*)(C + (size_t)r0 * N + cb) = o0;
            *(float2*)(C + (size_t)(r0 + 8) * N + cb) = o1;
        }
    }
}

// ---------------- causal flash attention (fp32) -----------------------------
__global__ __launch_bounds__(128) void attn_kernel(
    const float* __restrict__ qkv, float* __restrict__ out)
{
    const int b  = blockIdx.z;
    const int h  = blockIdx.y;
    const int qi = blockIdx.x * 128 + threadIdx.x;

    __shared__ float Ks[64][DHEAD];
    __shared__ float Vs[64][DHEAD];

    float q[DHEAD];
    {
        const float* qp = qkv + ((size_t)(b * TSEQ + qi)) * QKV_N + h * DHEAD;
#pragma unroll
        for (int d = 0; d < DHEAD; d += 4) {
            float4 v = *(const float4*)(qp + d);
            q[d + 0] = v.x * 0.125f;
            q[d + 1] = v.y * 0.125f;
            q[d + 2] = v.z * 0.125f;
            q[d + 3] = v.w * 0.125f;
        }
    }

    float acc[DHEAD];
#pragma unroll
    for (int d = 0; d < DHEAD; d++) acc[d] = 0.f;
    float m = -1e30f, l = 0.f;

    const int ntiles = blockIdx.x * 2 + 2;
    for (int kt = 0; kt < ntiles; kt++) {
        __syncthreads();
        for (int i = threadIdx.x; i < 64 * (DHEAD / 4); i += 128) {
            int r  = i >> 4;
            int c4 = i & 15;
            size_t base = ((size_t)(b * TSEQ + kt * 64 + r)) * QKV_N
                        + h * DHEAD + c4 * 4;
            *(float4*)&Ks[r][c4 * 4] = *(const float4*)(qkv + base + DMODEL);
            *(float4*)&Vs[r][c4 * 4] = *(const float4*)(qkv + base + 2 * DMODEL);
        }
        __syncthreads();

        const int kbase = kt * 64;
#pragma unroll 1
        for (int jc = 0; jc < 64; jc += 8) {
            float s[8];
#pragma unroll
            for (int j = 0; j < 8; j++) s[j] = 0.f;
#pragma unroll
            for (int d4 = 0; d4 < DHEAD / 4; d4++) {
                float q0 = q[d4*4+0], q1 = q[d4*4+1], q2 = q[d4*4+2], q3 = q[d4*4+3];
#pragma unroll
                for (int j = 0; j < 8; j++) {
                    float4 kv = *(const float4*)&Ks[jc + j][d4 * 4];
                    s[j] = fmaf(q0, kv.x, s[j]);
                    s[j] = fmaf(q1, kv.y, s[j]);
                    s[j] = fmaf(q2, kv.z, s[j]);
                    s[j] = fmaf(q3, kv.w, s[j]);
                }
            }
            float mloc = m;
#pragma unroll
            for (int j = 0; j < 8; j++) {
                if (kbase + jc + j > qi) s[j] = -1e30f;
                mloc = fmaxf(mloc, s[j]);
            }
            if (mloc > m) {
                float corr = __expf(m - mloc);
                l *= corr;
#pragma unroll
                for (int d = 0; d < DHEAD; d++) acc[d] *= corr;
                m = mloc;
            }
            float p[8];
#pragma unroll
            for (int j = 0; j < 8; j++) {
                p[j] = __expf(s[j] - m);
                l += p[j];
            }
#pragma unroll
            for (int d4 = 0; d4 < DHEAD / 4; d4++) {
                float a0 = acc[d4*4+0], a1 = acc[d4*4+1],
                      a2 = acc[d4*4+2], a3 = acc[d4*4+3];
#pragma unroll
                for (int j = 0; j < 8; j++) {
                    float4 vv = *(const float4*)&Vs[jc + j][d4 * 4];
                    a0 = fmaf(p[j], vv.x, a0);
                    a1 = fmaf(p[j], vv.y, a1);
                    a2 = fmaf(p[j], vv.z, a2);
                    a3 = fmaf(p[j], vv.w, a3);
                }
                acc[d4*4+0] = a0; acc[d4*4+1] = a1;
                acc[d4*4+2] = a2; acc[d4*4+3] = a3;
            }
        }
    }

    const float inv = 1.f / l;
    float* op = out + ((size_t)(b * TSEQ + qi)) * DMODEL + h * DHEAD;
#pragma unroll
    for (int d = 0; d < DHEAD; d += 4) {
        float4 o;
        o.x = rna_tf32(acc[d + 0] * inv);   // pre-round for tf32 proj GEMM
        o.y = rna_tf32(acc[d + 1] * inv);
        o.z = rna_tf32(acc[d + 2] * inv);
        o.w = rna_tf32(acc[d + 3] * inv);
        *(float4*)(op + d) = o;
    }
}

// ---------------------------------------------------------------------------
extern "C" void kernel_launch(void* const* d_in, const int* in_sizes, int n_in,
                              void* d_out, int out_size)
{
    const float* x      = (const float*)d_in[0];   // [2,2048,1024]
    const float* W_attn = (const float*)d_in[1];   // [1024,3072]
    const float* b_attn = (const float*)d_in[2];   // [3072]
    const float* W_proj = (const float*)d_in[3];   // [1024,1024]
    const float* b_proj = (const float*)d_in[4];   // [1024]
    float* out = (float*)d_out;                    // [2,2048,1024]

    float *qkv, *attn, *xr, *wta, *wtp;
    cudaGetSymbolAddress((void**)&qkv,  g_qkv);
    cudaGetSymbolAddress((void**)&attn, g_attn);
    cudaGetSymbolAddress((void**)&xr,   g_xr);
    cudaGetSymbolAddress((void**)&wta,  g_wt_attn);
    cudaGetSymbolAddress((void**)&wtp,  g_wt_proj);

    cudaFuncSetAttribute(gemm_tf32_mma,
                         cudaFuncAttributeMaxDynamicSharedMemorySize, GEMM_SMEM);

    // prep: tf32-round x; transpose+round weights
    {
        int n4 = BT * DMODEL / 4;
        round_tf32_kernel<<<(n4 + 255) / 256, 256>>>((const float4*)x, (float4*)xr, n4);
        transpose_rna_kernel<<<dim3(QKV_N / 32, KDIM / 32), dim3(32, 8)>>>(W_attn, wta, KDIM, QKV_N);
        transpose_rna_kernel<<<dim3(DMODEL / 32, KDIM / 32), dim3(32, 8)>>>(W_proj, wtp, KDIM, DMODEL);
    }
    // 1) QKV projection (tf32 tensor cores via mma.sync)
    gemm_tf32_mma<<<dim3(QKV_N / 128, BT / 128), 256, GEMM_SMEM>>>(xr, wta, b_attn, qkv, QKV_N);
    // 2) causal attention (fp32)
    {
        dim3 grid(TSEQ / 128, NHEAD, BATCH);
        attn_kernel<<<grid, 128>>>(qkv, attn);
    }
    // 3) output projection (tf32 tensor cores via mma.sync)
    gemm_tf32_mma<<<dim3(DMODEL / 128, BT / 128), 256, GEMM_SMEM>>>(attn, wtp, b_proj, out, DMODEL);
}

// round 4
// speedup vs baseline: 4.1581x; 2.7859x over previous
#include <cuda_runtime.h>
#include <cstdint>
#include <math.h>

#define BATCH 2
#define TSEQ  2048
#define DMODEL 1024
#define NHEAD 16
#define DHEAD 64
#define BT (BATCH * TSEQ)          // 4096
#define QKV_N (3 * DMODEL)         // 3072
#define KDIM DMODEL                // K = 1024 for both GEMMs

// ---------------- scratch (device globals; allocation-free rule) ----------
__device__ __align__(256) float g_qkv[(size_t)BT * QKV_N];       // [4096,3072]
__device__ __align__(256) float g_attn[(size_t)BT * DMODEL];     // [4096,1024]
__device__ __align__(256) float g_xr[(size_t)BT * DMODEL];       // x, tf32-rounded
__device__ __align__(256) float g_wt_attn[(size_t)QKV_N * KDIM]; // W_attn^T [3072,1024]
__device__ __align__(256) float g_wt_proj[(size_t)DMODEL * KDIM];// W_proj^T [1024,1024]

// ---------------- helpers ---------------------------------------------------
__device__ __forceinline__ uint32_t smem_u32(const void* p) {
    uint32_t a;
    asm("{ .reg .u64 t; cvta.to.shared.u64 t, %1; cvt.u32.u64 %0, t; }" : "=r"(a) : "l"(p));
    return a;
}
__device__ __forceinline__ float rna_tf32(float x) {
    float r;
    asm("cvt.rna.tf32.f32 %0, %1;" : "=f"(r) : "f"(x));
    return r;
}
__device__ __forceinline__ float ex2f(float x) {
    float r;
    asm("ex2.approx.f32 %0, %1;" : "=f"(r) : "f"(x));
    return r;
}
__device__ __forceinline__ void cp_async16(uint32_t saddr, const void* gptr) {
    asm volatile("cp.async.cg.shared.global [%0], [%1], 16;" :: "r"(saddr), "l"(gptr));
}
__device__ __forceinline__ void mma_tf32_16n8k8(float* d, const uint32_t* a, const uint32_t* b) {
    asm volatile(
        "mma.sync.aligned.m16n8k8.row.col.f32.tf32.tf32.f32 "
        "{%0,%1,%2,%3}, {%4,%5,%6,%7}, {%8,%9}, {%0,%1,%2,%3};"
        : "+f"(d[0]), "+f"(d[1]), "+f"(d[2]), "+f"(d[3])
        : "r"(a[0]), "r"(a[1]), "r"(a[2]), "r"(a[3]), "r"(b[0]), "r"(b[1]));
}

// ---------------- prep kernels ---------------------------------------------
__global__ void round_tf32_kernel(const float4* __restrict__ src,
                                  float4* __restrict__ dst, int n4) {
    int i = blockIdx.x * blockDim.x + threadIdx.x;
    if (i < n4) {
        float4 v = src[i];
        v.x = rna_tf32(v.x); v.y = rna_tf32(v.y);
        v.z = rna_tf32(v.z); v.w = rna_tf32(v.w);
        dst[i] = v;
    }
}

// Wt[n][k] = rna(W[k][n]);  W is [K, N] row-major
__global__ void transpose_rna_kernel(const float* __restrict__ W,
                                     float* __restrict__ Wt, int K, int N) {
    __shared__ float tile[32][33];
    int nx = blockIdx.x * 32, kx = blockIdx.y * 32;
    for (int i = threadIdx.y; i < 32; i += 8)
        tile[i][threadIdx.x] = W[(size_t)(kx + i) * N + nx + threadIdx.x];
    __syncthreads();
    for (int i = threadIdx.y; i < 32; i += 8)
        Wt[(size_t)(nx + i) * K + kx + threadIdx.x] = rna_tf32(tile[threadIdx.x][i]);
}

// ---------------- tf32 mma.sync GEMM (unchanged from R3, passing) ----------
#define GSTRIDE 36
#define GBUF (128 * GSTRIDE)
#define GEMM_SMEM (2 * 2 * GBUF * 4)

__global__ __launch_bounds__(256) void gemm_tf32_mma(
    const float* __restrict__ A, const float* __restrict__ Bt,
    const float* __restrict__ bias, float* __restrict__ C, int N)
{
    extern __shared__ float sm[];
    float* As = sm;
    float* Bs = sm + 2 * GBUF;

    const int tid = threadIdx.x, wid = tid >> 5, lid = tid & 31;
    const int m0 = blockIdx.y * 128, n0 = blockIdx.x * 128;
    const int m_warp = (wid >> 2) * 64;
    const int n_warp = (wid & 3) * 32;

    const uint32_t sA = smem_u32(As), sB = smem_u32(Bs);

    float acc[4][4][4];
#pragma unroll
    for (int i = 0; i < 4; i++)
#pragma unroll
        for (int j = 0; j < 4; j++)
#pragma unroll
            for (int q = 0; q < 4; q++) acc[i][j][q] = 0.f;

    auto load_stage = [&](int c, int buf) {
        const int k0 = c * 32;
#pragma unroll
        for (int i = 0; i < 4; i++) {
            int ch = tid + i * 256;
            int row = ch >> 3, c16 = ch & 7;
            uint32_t so = (uint32_t)((buf * GBUF + row * GSTRIDE + c16 * 4) * 4);
            cp_async16(sA + so, A + (size_t)(m0 + row) * KDIM + k0 + c16 * 4);
            cp_async16(sB + so, Bt + (size_t)(n0 + row) * KDIM + k0 + c16 * 4);
        }
        asm volatile("cp.async.commit_group;" ::: "memory");
    };

    load_stage(0, 0);

    const int NCHUNK = KDIM / 32;
    for (int c = 0; c < NCHUNK; c++) {
        if (c + 1 < NCHUNK) {
            load_stage(c + 1, (c + 1) & 1);
            asm volatile("cp.async.wait_group 1;" ::: "memory");
        } else {
            asm volatile("cp.async.wait_group 0;" ::: "memory");
        }
        __syncthreads();

        const float* Ab = As + (c & 1) * GBUF;
        const float* Bb = Bs + (c & 1) * GBUF;
#pragma unroll
        for (int ks = 0; ks < 4; ks++) {
            const int k_lo = ks * 8 + (lid & 3);
            uint32_t af[4][4], bf[4][2];
#pragma unroll
            for (int mt = 0; mt < 4; mt++) {
                int r0 = m_warp + mt * 16 + (lid >> 2);
                af[mt][0] = __float_as_uint(Ab[r0 * GSTRIDE + k_lo]);
                af[mt][1] = __float_as_uint(Ab[(r0 + 8) * GSTRIDE + k_lo]);
                af[mt][2] = __float_as_uint(Ab[r0 * GSTRIDE + k_lo + 4]);
                af[mt][3] = __float_as_uint(Ab[(r0 + 8) * GSTRIDE + k_lo + 4]);
            }
#pragma unroll
            for (int nt = 0; nt < 4; nt++) {
                int nc = n_warp + nt * 8 + (lid >> 2);
                bf[nt][0] = __float_as_uint(Bb[nc * GSTRIDE + k_lo]);
                bf[nt][1] = __float_as_uint(Bb[nc * GSTRIDE + k_lo + 4]);
            }
#pragma unroll
            for (int mt = 0; mt < 4; mt++)
#pragma unroll
                for (int nt = 0; nt < 4; nt++)
                    mma_tf32_16n8k8(acc[mt][nt], af[mt], bf[nt]);
        }
        __syncthreads();
    }

#pragma unroll
    for (int mt = 0; mt < 4; mt++) {
        int r0 = m0 + m_warp + mt * 16 + (lid >> 2);
#pragma unroll
        for (int nt = 0; nt < 4; nt++) {
            int cb = n0 + n_warp + nt * 8 + 2 * (lid & 3);
            float2 bz = *(const float2*)(bias + cb);
            float2 o0, o1;
            o0.x = acc[mt][nt][0] + bz.x; o0.y = acc[mt][nt][1] + bz.y;
            o1.x = acc[mt][nt][2] + bz.x; o1.y = acc[mt][nt][3] + bz.y;
            *(float2*)(C + (size_t)r0 * N + cb) = o0;
            *(float2*)(C + (size_t)(r0 + 8) * N + cb) = o1;
        }
    }
}

// ---------------- tf32 mma flash attention ---------------------------------
// CTA: 128 queries, 4 warps (each owns 32 query rows = 2 m16 tiles).
// Key tiles of 128, processed as two 64-key subtiles (bounds S-register count).
// smem tiles [128][68]: stride 68 -> (4r+c)%32 bank permutation, conflict-free
// for all fragment load patterns used here.
#define ATPAD 68
#define ATT_SMEM (3 * 128 * ATPAD * 4)   // 104448 bytes

__global__ __launch_bounds__(128) void attn_mma_kernel(
    const float* __restrict__ qkv, float* __restrict__ out)
{
    extern __shared__ float sm[];
    float* Qs  = sm;                     // [128][ATPAD]
    float* Ksm = sm + 128 * ATPAD;       // [128][ATPAD]
    float* Vsm = sm + 2 * 128 * ATPAD;   // [128][ATPAD]

    const int tid = threadIdx.x, wid = tid >> 5, lid = tid & 31;
    const int cq = lid & 3, rq = lid >> 2;
    const int b = blockIdx.z, h = blockIdx.y;
    const int bx = (int)gridDim.x - 1 - (int)blockIdx.x;   // heavy blocks first
    const int q0 = bx * 128;
    const float* base = qkv + (size_t)b * TSEQ * QKV_N + h * DHEAD;

    const uint32_t sQ = smem_u32(Qs), sK = smem_u32(Ksm), sV = smem_u32(Vsm);

    // Q tile: 128 rows x 16 float4 chunks
#pragma unroll
    for (int i = 0; i < 16; i++) {
        int ch = tid + i * 128;
        int r = ch >> 4, c4 = ch & 15;
        cp_async16(sQ + (uint32_t)(r * ATPAD + c4 * 4) * 4,
                   base + (size_t)(q0 + r) * QKV_N + c4 * 4);
    }
    asm volatile("cp.async.commit_group;" ::: "memory");

    float acc[2][8][4];
#pragma unroll
    for (int mt = 0; mt < 2; mt++)
#pragma unroll
        for (int nt = 0; nt < 8; nt++)
#pragma unroll
            for (int j = 0; j < 4; j++) acc[mt][nt][j] = 0.f;
    float mrow[2][2], lrow[2][2];
#pragma unroll
    for (int mt = 0; mt < 2; mt++) {
        mrow[mt][0] = -1e30f; mrow[mt][1] = -1e30f;
        lrow[mt][0] = 0.f;    lrow[mt][1] = 0.f;
    }

    const int mrow0 = wid * 32;
    const float SC = 0.1803368801111f;   // (1/8) * log2(e)

    asm volatile("cp.async.wait_group 0;" ::: "memory");
    __syncthreads();

#pragma unroll 1
    for (int kt = 0; kt <= bx; kt++) {
        __syncthreads();    // previous subtile compute done before overwrite
#pragma unroll
        for (int i = 0; i < 16; i++) {
            int ch = tid + i * 128;
            int r = ch >> 4, c4 = ch & 15;
            const float* g = base + (size_t)(kt * 128 + r) * QKV_N + c4 * 4;
            uint32_t so = (uint32_t)(r * ATPAD + c4 * 4) * 4;
            cp_async16(sK + so, g + DMODEL);
            cp_async16(sV + so, g + 2 * DMODEL);
        }
        asm volatile("cp.async.commit_group;" ::: "memory");
        asm volatile("cp.async.wait_group 0;" ::: "memory");
        __syncthreads();

#pragma unroll 1
        for (int sub = 0; sub < 2; sub++) {
            const int kb = sub * 64;

            // ---- S = Q @ K^T (2 mtiles x 8 ntiles) ----
            float s[2][8][4];
#pragma unroll
            for (int mt = 0; mt < 2; mt++)
#pragma unroll
                for (int nt = 0; nt < 8; nt++)
#pragma unroll
                    for (int j = 0; j < 4; j++) s[mt][nt][j] = 0.f;

#pragma unroll
            for (int ks = 0; ks < 8; ks++) {
                uint32_t af[2][4];
#pragma unroll
                for (int mt = 0; mt < 2; mt++) {
                    const float* qb = Qs + (mrow0 + mt * 16 + rq) * ATPAD + ks * 8 + cq;
                    af[mt][0] = __float_as_uint(qb[0]);
                    af[mt][1] = __float_as_uint(qb[8 * ATPAD]);
                    af[mt][2] = __float_as_uint(qb[4]);
                    af[mt][3] = __float_as_uint(qb[8 * ATPAD + 4]);
                }
#pragma unroll
                for (int nt = 0; nt < 8; nt++) {
                    uint32_t bf[2];
                    const float* kp = Ksm + (kb + nt * 8 + rq) * ATPAD + ks * 8 + cq;
                    bf[0] = __float_as_uint(kp[0]);
                    bf[1] = __float_as_uint(kp[4]);
                    mma_tf32_16n8k8(s[0][nt], af[0], bf);
                    mma_tf32_16n8k8(s[1][nt], af[1], bf);
                }
            }

            // ---- scale, causal mask, online softmax (base-2) ----
#pragma unroll
            for (int mt = 0; mt < 2; mt++) {
#pragma unroll
                for (int nt = 0; nt < 8; nt++)
#pragma unroll
                    for (int j = 0; j < 4; j++) s[mt][nt][j] *= SC;

                if (kt == bx) {
                    int row0 = mrow0 + mt * 16 + rq;
#pragma unroll
                    for (int nt = 0; nt < 8; nt++) {
                        int c0 = kb + nt * 8 + 2 * cq;
                        if (c0     > row0)     s[mt][nt][0] = -1e30f;
                        if (c0 + 1 > row0)     s[mt][nt][1] = -1e30f;
                        if (c0     > row0 + 8) s[mt][nt][2] = -1e30f;
                        if (c0 + 1 > row0 + 8) s[mt][nt][3] = -1e30f;
                    }
                }

                float mx0 = -1e30f, mx1 = -1e30f;
#pragma unroll
                for (int nt = 0; nt < 8; nt++) {
                    mx0 = fmaxf(mx0, fmaxf(s[mt][nt][0], s[mt][nt][1]));
                    mx1 = fmaxf(mx1, fmaxf(s[mt][nt][2], s[mt][nt][3]));
                }
                mx0 = fmaxf(mx0, __shfl_xor_sync(0xffffffffu, mx0, 1));
                mx0 = fmaxf(mx0, __shfl_xor_sync(0xffffffffu, mx0, 2));
                mx1 = fmaxf(mx1, __shfl_xor_sync(0xffffffffu, mx1, 1));
                mx1 = fmaxf(mx1, __shfl_xor_sync(0xffffffffu, mx1, 2));

                float mn0 = fmaxf(mrow[mt][0], mx0);
                float mn1 = fmaxf(mrow[mt][1], mx1);
                float sc0 = ex2f(mrow[mt][0] - mn0);
                float sc1 = ex2f(mrow[mt][1] - mn1);
                mrow[mt][0] = mn0; mrow[mt][1] = mn1;
                lrow[mt][0] *= sc0; lrow[mt][1] *= sc1;
#pragma unroll
                for (int nt = 0; nt < 8; nt++) {
                    acc[mt][nt][0] *= sc0; acc[mt][nt][1] *= sc0;
                    acc[mt][nt][2] *= sc1; acc[mt][nt][3] *= sc1;
                }
                float su0 = 0.f, su1 = 0.f;
#pragma unroll
                for (int nt = 0; nt < 8; nt++) {
                    s[mt][nt][0] = ex2f(s[mt][nt][0] - mn0); su0 += s[mt][nt][0];
                    s[mt][nt][1] = ex2f(s[mt][nt][1] - mn0); su0 += s[mt][nt][1];
                    s[mt][nt][2] = ex2f(s[mt][nt][2] - mn1); su1 += s[mt][nt][2];
                    s[mt][nt][3] = ex2f(s[mt][nt][3] - mn1); su1 += s[mt][nt][3];
                }
                su0 += __shfl_xor_sync(0xffffffffu, su0, 1);
                su0 += __shfl_xor_sync(0xffffffffu, su0, 2);
                su1 += __shfl_xor_sync(0xffffffffu, su1, 1);
                su1 += __shfl_xor_sync(0xffffffffu, su1, 2);
                lrow[mt][0] += su0; lrow[mt][1] += su1;
            }

            // ---- O += P @ V ----
            const int src  = (lid & 28) | ((lid >> 1) & 1);
            const int src2 = src + 2;
#pragma unroll
            for (int k8 = 0; k8 < 8; k8++) {
                uint32_t pa[2][4];
#pragma unroll
                for (int mt = 0; mt < 2; mt++) {
                    float v0 = __shfl_sync(0xffffffffu, s[mt][k8][0], src);
                    float v1 = __shfl_sync(0xffffffffu, s[mt][k8][1], src);
                    float w0 = __shfl_sync(0xffffffffu, s[mt][k8][0], src2);
                    float w1 = __shfl_sync(0xffffffffu, s[mt][k8][1], src2);
                    float x0 = __shfl_sync(0xffffffffu, s[mt][k8][2], src);
                    float x1 = __shfl_sync(0xffffffffu, s[mt][k8][3], src);
                    float y0 = __shfl_sync(0xffffffffu, s[mt][k8][2], src2);
                    float y1 = __shfl_sync(0xffffffffu, s[mt][k8][3], src2);
                    bool e = (lid & 1) != 0;
                    pa[mt][0] = __float_as_uint(e ? v1 : v0);
                    pa[mt][2] = __float_as_uint(e ? w1 : w0);
                    pa[mt][1] = __float_as_uint(e ? x1 : x0);
                    pa[mt][3] = __float_as_uint(e ? y1 : y0);
                }
#pragma unroll
                for (int nt = 0; nt < 8; nt++) {
                    uint32_t bf[2];
                    const float* vb = Vsm + (kb + k8 * 8 + cq) * ATPAD + nt * 8 + rq;
                    bf[0] = __float_as_uint(vb[0]);
                    bf[1] = __float_as_uint(vb[4 * ATPAD]);
                    mma_tf32_16n8k8(acc[0][nt], pa[0], bf);
                    mma_tf32_16n8k8(acc[1][nt], pa[1], bf);
                }
            }
        }
    }

    // ---- epilogue: normalize, tf32-round (feeds proj GEMM), store ----
    float* outp = out + (size_t)b * TSEQ * DMODEL + h * DHEAD;
#pragma unroll
    for (int mt = 0; mt < 2; mt++) {
        float i0 = 1.f / lrow[mt][0], i1 = 1.f / lrow[mt][1];
        int row0 = q0 + mrow0 + mt * 16 + rq;
#pragma unroll
        for (int nt = 0; nt < 8; nt++) {
            int col = nt * 8 + 2 * cq;
            float2 o0, o1;
            o0.x = rna_tf32(acc[mt][nt][0] * i0);
            o0.y = rna_tf32(acc[mt][nt][1] * i0);
            o1.x = rna_tf32(acc[mt][nt][2] * i1);
            o1.y = rna_tf32(acc[mt][nt][3] * i1);
            *(float2*)(outp + (size_t)row0 * DMODEL + col) = o0;
            *(float2*)(outp + (size_t)(row0 + 8) * DMODEL + col) = o1;
        }
    }
}

// ---------------------------------------------------------------------------
extern "C" void kernel_launch(void* const* d_in, const int* in_sizes, int n_in,
                              void* d_out, int out_size)
{
    const float* x      = (const float*)d_in[0];   // [2,2048,1024]
    const float* W_attn = (const float*)d_in[1];   // [1024,3072]
    const float* b_attn = (const float*)d_in[2];   // [3072]
    const float* W_proj = (const float*)d_in[3];   // [1024,1024]
    const float* b_proj = (const float*)d_in[4];   // [1024]
    float* out = (float*)d_out;                    // [2,2048,1024]

    float *qkv, *attn, *xr, *wta, *wtp;
    cudaGetSymbolAddress((void**)&qkv,  g_qkv);
    cudaGetSymbolAddress((void**)&attn, g_attn);
    cudaGetSymbolAddress((void**)&xr,   g_xr);
    cudaGetSymbolAddress((void**)&wta,  g_wt_attn);
    cudaGetSymbolAddress((void**)&wtp,  g_wt_proj);

    cudaFuncSetAttribute(gemm_tf32_mma,
                         cudaFuncAttributeMaxDynamicSharedMemorySize, GEMM_SMEM);
    cudaFuncSetAttribute(attn_mma_kernel,
                         cudaFuncAttributeMaxDynamicSharedMemorySize, ATT_SMEM);

    // prep: tf32-round x; transpose+round weights
    {
        int n4 = BT * DMODEL / 4;
        round_tf32_kernel<<<(n4 + 255) / 256, 256>>>((const float4*)x, (float4*)xr, n4);
        transpose_rna_kernel<<<dim3(QKV_N / 32, KDIM / 32), dim3(32, 8)>>>(W_attn, wta, KDIM, QKV_N);
        transpose_rna_kernel<<<dim3(DMODEL / 32, KDIM / 32), dim3(32, 8)>>>(W_proj, wtp, KDIM, DMODEL);
    }
    // 1) QKV projection (tf32 mma.sync)
    gemm_tf32_mma<<<dim3(QKV_N / 128, BT / 128), 256, GEMM_SMEM>>>(xr, wta, b_attn, qkv, QKV_N);
    // 2) causal attention (tf32 mma.sync flash attention)
    {
        dim3 grid(TSEQ / 128, NHEAD, BATCH);
        attn_mma_kernel<<<grid, 128, ATT_SMEM>>>(qkv, attn);
    }
    // 3) output projection (tf32 mma.sync)
    gemm_tf32_mma<<<dim3(DMODEL / 128, BT / 128), 256, GEMM_SMEM>>>(attn, wtp, b_proj, out, DMODEL);
}